// round 9
// baseline (speedup 1.0000x reference)
#include <cuda_runtime.h>
#include <cuda_bf16.h>
#include <cstdint>

static constexpr int BATCH = 8;
static constexpr int LQ    = 2048;
static constexpr int LKV   = 2048;
static constexpr int DIM   = 128;   // D == DV == 128
static constexpr float SM_SCALE = 0.08838834764831845f; // 1/sqrt(128)

// Scratch (device globals; no runtime allocation allowed)
__device__ __align__(128) __nv_bfloat16 g_Qh[(size_t)BATCH * LQ  * DIM];
__device__ __align__(128) __nv_bfloat16 g_Ql[(size_t)BATCH * LQ  * DIM];
__device__ __align__(128) __nv_bfloat16 g_Kh[(size_t)BATCH * LKV * DIM];
__device__ __align__(128) __nv_bfloat16 g_Kl[(size_t)BATCH * LKV * DIM];
__device__ __align__(128) __nv_bfloat16 g_Vt_hi[(size_t)BATCH * DIM * LKV]; // [B][DV][LKV]
__device__ __align__(128) __nv_bfloat16 g_Vt_lo[(size_t)BATCH * DIM * LKV];
__device__ __align__(128) __nv_bfloat16 g_Eh[(size_t)BATCH * LQ * LKV];     // exp(S) hi
__device__ __align__(128) __nv_bfloat16 g_El[(size_t)BATCH * LQ * LKV];     // exp(S) lo
// per-row partial exp-sums: [B*LQ][32]  (16 n-tiles x 2 n-warps), deterministic
__device__ __align__(128) float g_partial[(size_t)BATCH * LQ * 32];
// K-split context partials: [2][B][LQ][DV]
__device__ __align__(128) float g_Cp[(size_t)2 * BATCH * LQ * DIM];

// ---------------------------------------------------------------------------
// Helpers (compute_103-safe: ldmatrix / mma.sync / cp.async only)
// ---------------------------------------------------------------------------
__device__ __forceinline__ uint32_t smem_u32(const void* p) {
    uint32_t a;
    asm("{ .reg .u64 t; cvta.to.shared.u64 t, %1; cvt.u32.u64 %0, t; }"
        : "=r"(a) : "l"(p));
    return a;
}
__device__ __forceinline__ uint32_t swz(uint32_t off) {     // SW128 (128B rows)
    return off ^ ((off >> 3) & 0x70);
}
__device__ __forceinline__ uint32_t swz64(uint32_t off) {   // SW64 (64B rows)
    return off ^ ((off >> 3) & 0x30);
}
__device__ __forceinline__ uint32_t pack2(__nv_bfloat16 a, __nv_bfloat16 b) {
    __nv_bfloat162 t(a, b);
    return *reinterpret_cast<uint32_t*>(&t);
}
__device__ __forceinline__ void split1(float v, __nv_bfloat16& h, __nv_bfloat16& l) {
    h = __float2bfloat16(v);
    l = __float2bfloat16(v - __bfloat162float(h));
}
__device__ __forceinline__ void split4(float4 v, uint2& hi, uint2& lo) {
    __nv_bfloat16 h0, h1, h2, h3, l0, l1, l2, l3;
    split1(v.x, h0, l0); split1(v.y, h1, l1);
    split1(v.z, h2, l2); split1(v.w, h3, l3);
    hi.x = pack2(h0, h1); hi.y = pack2(h2, h3);
    lo.x = pack2(l0, l1); lo.y = pack2(l2, l3);
}
__device__ __forceinline__ float2 bf2f(uint32_t u) {
    __nv_bfloat162 t = *reinterpret_cast<__nv_bfloat162*>(&u);
    return __bfloat1622float2(t);
}
__device__ __forceinline__ uint2 lds8(uint32_t addr) {
    uint2 v;
    asm volatile("ld.shared.v2.b32 {%0,%1}, [%2];" : "=r"(v.x), "=r"(v.y) : "r"(addr));
    return v;
}
__device__ __forceinline__ void ldsm4(uint32_t* r, uint32_t addr) {
    asm volatile("ldmatrix.sync.aligned.m8n8.x4.shared.b16 {%0,%1,%2,%3}, [%4];"
                 : "=r"(r[0]), "=r"(r[1]), "=r"(r[2]), "=r"(r[3]) : "r"(addr));
}
__device__ __forceinline__ void mma_bf16(float* d, const uint32_t* a, const uint32_t* b) {
    asm volatile("mma.sync.aligned.m16n8k16.row.col.f32.bf16.bf16.f32 "
                 "{%0,%1,%2,%3}, {%4,%5,%6,%7}, {%8,%9}, {%0,%1,%2,%3};"
                 : "+f"(d[0]), "+f"(d[1]), "+f"(d[2]), "+f"(d[3])
                 : "r"(a[0]), "r"(a[1]), "r"(a[2]), "r"(a[3]), "r"(b[0]), "r"(b[1]));
}
#define CP_ASYNC16(dst, src) \
    asm volatile("cp.async.cg.shared.global [%0], [%1], 16;" :: "r"(dst), "l"(src) : "memory")
#define CP_COMMIT()  asm volatile("cp.async.commit_group;" ::: "memory")
#define CP_WAIT(n)   asm volatile("cp.async.wait_group %0;" :: "n"(n) : "memory")

// ---------------------------------------------------------------------------
// Prep A: split Q(*scale) and K into bf16 hi/lo scratch (row-major unchanged)
// ---------------------------------------------------------------------------
__global__ __launch_bounds__(256) void qk_split_kernel(
    const float* __restrict__ Q, const float* __restrict__ K)
{
    const size_t t = (size_t)blockIdx.x * 256 + threadIdx.x;   // float4 index
    const bool isK = blockIdx.y != 0;
    const float4 v4 = ((const float4*)(isK ? K : Q))[t];
    float4 v = v4;
    if (!isK) { v.x *= SM_SCALE; v.y *= SM_SCALE; v.z *= SM_SCALE; v.w *= SM_SCALE; }
    uint2 hi, lo; split4(v, hi, lo);
    ((uint2*)(isK ? g_Kh : g_Qh))[t] = hi;
    ((uint2*)(isK ? g_Kl : g_Ql))[t] = lo;
}

// ---------------------------------------------------------------------------
// Prep B: transpose + bf16-split V:  V[b][k][n] -> Vt_hi/lo[b][n][k]
// ---------------------------------------------------------------------------
__global__ __launch_bounds__(256) void vt_split_kernel(const float* __restrict__ V)
{
    __shared__ float t[32][33];
    const int b  = blockIdx.z;
    const int k0 = blockIdx.y * 32;
    const int n0 = blockIdx.x * 32;
    const int tx = threadIdx.x & 31;
    const int ty = threadIdx.x >> 5;   // 0..7

    #pragma unroll
    for (int i = 0; i < 4; i++) {
        int k = ty + i * 8;
        t[k][tx] = V[((size_t)b * LKV + k0 + k) * DIM + n0 + tx];
    }
    __syncthreads();
    #pragma unroll
    for (int i = 0; i < 4; i++) {
        int n = ty + i * 8;
        float x = t[tx][n];
        __nv_bfloat16 h, l;
        split1(x, h, l);
        size_t o = ((size_t)b * DIM + n0 + n) * LKV + k0 + tx;
        g_Vt_hi[o] = h;
        g_Vt_lo[o] = l;
    }
}

// ---------------------------------------------------------------------------
// GEMM1: E = exp((Q*scale) K^T) via mma.sync bf16x3, pure-bf16 operands.
// CTA tile 128x128, 8 warps (warp tile 32x64).  K=128 in 4 chunks of 32,
// 2-stage cp.async pipeline (SW64 smem, 32KB/stage), one barrier per chunk,
// prefetch issued after the barrier (race-free: barrier proves all warps
// left chunk c-1 whose buffer the prefetch of c+1 overwrites).
// ---------------------------------------------------------------------------
static constexpr int G1_SMEM = 1024 + 2 * 32768;

__global__ __launch_bounds__(256, 2) void gemm1_mma_kernel()
{
    extern __shared__ char smem[];
    const uint32_t sb = (smem_u32(smem) + 1023u) & ~1023u;

    const int tid  = threadIdx.x;
    const int lane = tid & 31;
    const int w    = tid >> 5;
    const int wm   = (w >> 1) * 32;   // 4 warps in M
    const int wn   = (w & 1) * 64;    // 2 warps in N

    const int b  = blockIdx.z;
    const int m0 = blockIdx.y * 128;
    const int n0 = blockIdx.x * 128;

    const __nv_bfloat16* Qh = g_Qh + ((size_t)b * LQ  + m0) * DIM;
    const __nv_bfloat16* Ql = g_Ql + ((size_t)b * LQ  + m0) * DIM;
    const __nv_bfloat16* Kh = g_Kh + ((size_t)b * LKV + n0) * DIM;
    const __nv_bfloat16* Kl = g_Kl + ((size_t)b * LKV + n0) * DIM;

    // stage layout: QH +0, QL +8192, KH +16384, KL +24576 (each 128x32 bf16)
    auto load_chunk = [&](int c, int stage) {
        const int k0 = c * 32;
        const uint32_t base = sb + (uint32_t)stage * 32768u;
        #pragma unroll
        for (int i = 0; i < 2; i++) {
            int u = i * 256 + tid;          // 0..511
            int row = u >> 2, c8 = (u & 3) * 8;
            uint32_t off = swz64((uint32_t)row * 64u + (uint32_t)c8 * 2u);
            CP_ASYNC16(base + off,           Qh + (size_t)row * DIM + k0 + c8);
            CP_ASYNC16(base + 8192u + off,   Ql + (size_t)row * DIM + k0 + c8);
            CP_ASYNC16(base + 16384u + off,  Kh + (size_t)row * DIM + k0 + c8);
            CP_ASYNC16(base + 24576u + off,  Kl + (size_t)row * DIM + k0 + c8);
        }
    };

    float acc[2][8][4] = {};

    const uint32_t a_row = lane & 15;
    const uint32_t a_kof = (lane >> 4) * 16;
    const uint32_t b_row = (lane & 7) + ((lane & 16) >> 1);
    const uint32_t b_kof = ((lane >> 3) & 1) * 16;

    load_chunk(0, 0);
    CP_COMMIT();

    for (int c = 0; c < 4; c++) {
        CP_WAIT(0);
        __syncthreads();   // chunk c resident; all warps past chunk c-1

        if (c < 3) { load_chunk(c + 1, (c + 1) & 1); CP_COMMIT(); }

        const uint32_t base = sb + (uint32_t)(c & 1) * 32768u;
        const uint32_t QHs = base, QLs = base + 8192u;
        const uint32_t KHs = base + 16384u, KLs = base + 24576u;

        #pragma unroll
        for (int ks = 0; ks < 2; ks++) {
            const uint32_t kb = ks * 32;   // bytes within 64B row
            uint32_t ah[2][4], al[2][4], bb[8][2];

            #pragma unroll
            for (int mf = 0; mf < 2; mf++) {
                uint32_t ro = (uint32_t)(wm + mf * 16 + a_row) * 64u + kb + a_kof;
                ldsm4(ah[mf], QHs + swz64(ro));
                ldsm4(al[mf], QLs + swz64(ro));
            }
            #pragma unroll
            for (int j = 0; j < 4; j++) {
                uint32_t ro = (uint32_t)(wn + j * 16 + b_row) * 64u + kb + b_kof;
                ldsm4(&bb[2 * j][0], KHs + swz64(ro));
            }
            #pragma unroll
            for (int mf = 0; mf < 2; mf++)
                #pragma unroll
                for (int nf = 0; nf < 8; nf++) {
                    mma_bf16(acc[mf][nf], ah[mf], bb[nf]);
                    mma_bf16(acc[mf][nf], al[mf], bb[nf]);
                }
            #pragma unroll
            for (int j = 0; j < 4; j++) {
                uint32_t ro = (uint32_t)(wn + j * 16 + b_row) * 64u + kb + b_kof;
                ldsm4(&bb[2 * j][0], KLs + swz64(ro));
            }
            #pragma unroll
            for (int mf = 0; mf < 2; mf++)
                #pragma unroll
                for (int nf = 0; nf < 8; nf++)
                    mma_bf16(acc[mf][nf], ah[mf], bb[nf]);
        }
    }

    // epilogue: exp, split to bf16 hi/lo, store; per-row partial sums
    const int er = lane >> 2;
    const int ec = (lane & 3) * 2;
    float rsum[2][2] = {{0.f, 0.f}, {0.f, 0.f}};
    #pragma unroll
    for (int mf = 0; mf < 2; mf++)
        #pragma unroll
        for (int nf = 0; nf < 8; nf++) {
            float e0 = __expf(fminf(acc[mf][nf][0], 80.f));
            float e1 = __expf(fminf(acc[mf][nf][1], 80.f));
            float e2 = __expf(fminf(acc[mf][nf][2], 80.f));
            float e3 = __expf(fminf(acc[mf][nf][3], 80.f));
            int r = m0 + wm + mf * 16 + er;
            int cc = n0 + wn + nf * 8 + ec;
            __nv_bfloat16 h0, l0, h1, l1;
            split1(e0, h0, l0); split1(e1, h1, l1);
            *(uint32_t*)(g_Eh + ((size_t)b * LQ + r) * LKV + cc) = pack2(h0, h1);
            *(uint32_t*)(g_El + ((size_t)b * LQ + r) * LKV + cc) = pack2(l0, l1);
            split1(e2, h0, l0); split1(e3, h1, l1);
            *(uint32_t*)(g_Eh + ((size_t)b * LQ + r + 8) * LKV + cc) = pack2(h0, h1);
            *(uint32_t*)(g_El + ((size_t)b * LQ + r + 8) * LKV + cc) = pack2(l0, l1);
            rsum[mf][0] += e0 + e1;
            rsum[mf][1] += e2 + e3;
        }
    #pragma unroll
    for (int mf = 0; mf < 2; mf++)
        #pragma unroll
        for (int h = 0; h < 2; h++) {
            float v = rsum[mf][h];
            v += __shfl_xor_sync(0xffffffffu, v, 1);
            v += __shfl_xor_sync(0xffffffffu, v, 2);
            if ((lane & 3) == 0) {
                int row = m0 + wm + mf * 16 + h * 8 + er;
                g_partial[((size_t)b * LQ + row) * 32 + blockIdx.x * 2 + (w & 1)] = v;
            }
        }
}

// ---------------------------------------------------------------------------
// GEMM2: K-split x2.  Each CTA: 64(M) x 128(N=DV) tile over HALF of K
// (16 chunks of 64).  Writes its K-half of W = E*inv (final fp32 weights)
// and a context partial (inv applied) into g_Cp[split].  cp.async double
// buffer, one barrier per chunk, prefetch-after-sync.
// ---------------------------------------------------------------------------
// per buffer (48KB): EH 8KB, EL 8KB (64x64 bf16), VH 16KB, VL 16KB (128x64)
static constexpr int G2_SMEM = 1024 + 2 * 49152 + 256;

__global__ __launch_bounds__(256, 2) void gemm2_mma_kernel(float* __restrict__ W)
{
    extern __shared__ char smem[];
    const uint32_t sb = (smem_u32(smem) + 1023u) & ~1023u;
    float* inv_s = (float*)(smem + (sb - smem_u32(smem)) + 2 * 49152);

    const int tid  = threadIdx.x;
    const int lane = tid & 31;
    const int w    = tid >> 5;
    const int wm   = (w >> 2) * 32;   // 2 warps in M
    const int wn   = (w & 3) * 32;    // 4 warps in N

    const int m0    = blockIdx.x * 64;
    const int b     = blockIdx.y;
    const int split = blockIdx.z;     // 0 or 1: K half

    float* Wb = W + ((size_t)b * LQ + m0) * LKV;
    const __nv_bfloat16* Eh = g_Eh + ((size_t)b * LQ + m0) * LKV;
    const __nv_bfloat16* El = g_El + ((size_t)b * LQ + m0) * LKV;
    const __nv_bfloat16* Vh = g_Vt_hi + (size_t)b * DIM * LKV;
    const __nv_bfloat16* Vl = g_Vt_lo + (size_t)b * DIM * LKV;
    float* Cp = g_Cp + ((size_t)split * BATCH + b) * LQ * DIM;

    // row inverse sums (deterministic reduction of 32 partials)
    if (tid < 64) {
        const float* p = g_partial + ((size_t)b * LQ + m0 + tid) * 32;
        float s = 0.f;
        #pragma unroll
        for (int j = 0; j < 32; j++) s += p[j];
        inv_s[tid] = 1.0f / s;
    }

    auto load_chunk = [&](int cc, int buf) {
        const int k0 = cc * 64;
        const uint32_t base = sb + (uint32_t)buf * 49152u;
        #pragma unroll
        for (int i = 0; i < 2; i++) {       // E tiles: 64 rows x 8 units
            int u = i * 256 + tid;
            int row = u >> 3, c8 = (u & 7) * 8;
            uint32_t off = swz((uint32_t)row * 128u + (uint32_t)c8 * 2u);
            CP_ASYNC16(base + off,          Eh + (size_t)row * LKV + k0 + c8);
            CP_ASYNC16(base + 8192u + off,  El + (size_t)row * LKV + k0 + c8);
        }
        #pragma unroll
        for (int i = 0; i < 4; i++) {       // V tiles: 128 rows x 8 units
            int u = i * 256 + tid;
            int row = u >> 3, c8 = (u & 7) * 8;
            uint32_t off = swz((uint32_t)row * 128u + (uint32_t)c8 * 2u);
            CP_ASYNC16(base + 16384u + off, Vh + (size_t)row * LKV + k0 + c8);
            CP_ASYNC16(base + 32768u + off, Vl + (size_t)row * LKV + k0 + c8);
        }
    };

    float acc[2][4][4] = {};

    const uint32_t a_row = lane & 15;
    const uint32_t a_kof = (lane >> 4) * 16;
    const uint32_t b_row = (lane & 7) + ((lane & 16) >> 1);
    const uint32_t b_kof = ((lane >> 3) & 1) * 16;

    const int c_base = split * 16;
    load_chunk(c_base, 0);
    CP_COMMIT();

    for (int c = 0; c < 16; c++) {
        CP_WAIT(0);
        __syncthreads();   // buf[c&1] resident; all warps past chunk c-1

        if (c < 15) { load_chunk(c_base + c + 1, (c + 1) & 1); CP_COMMIT(); }

        const int k0 = (c_base + c) * 64;
        const uint32_t base = sb + (uint32_t)(c & 1) * 49152u;
        const uint32_t EHt = base, ELt = base + 8192u;
        const uint32_t vh = base + 16384u, vl = base + 32768u;

        // W = (Eh + El) * inv  -> final fp32 weights (STGs drain during MMA)
        #pragma unroll
        for (int i = 0; i < 4; i++) {
            int u = i * 256 + tid;
            int row = u >> 4, c4 = (u & 15) * 4;
            uint32_t off = swz((uint32_t)row * 128u + (uint32_t)c4 * 2u);
            uint2 hh = lds8(EHt + off);
            uint2 ll = lds8(ELt + off);
            float2 h01 = bf2f(hh.x), h23 = bf2f(hh.y);
            float2 l01 = bf2f(ll.x), l23 = bf2f(ll.y);
            float inv = inv_s[row];
            float4 wv = make_float4((h01.x + l01.x) * inv, (h01.y + l01.y) * inv,
                                    (h23.x + l23.x) * inv, (h23.y + l23.y) * inv);
            *(float4*)(Wb + (size_t)row * LKV + k0 + c4) = wv;
        }

        #pragma unroll
        for (int ks = 0; ks < 4; ks++) {
            const uint32_t kb = ks * 32;
            uint32_t ah[2][4], al[2][4], bb[4][2];

            #pragma unroll
            for (int mf = 0; mf < 2; mf++) {
                uint32_t ro = (uint32_t)(wm + mf * 16 + a_row) * 128u + kb + a_kof;
                ldsm4(ah[mf], EHt + swz(ro));
                ldsm4(al[mf], ELt + swz(ro));
            }
            #pragma unroll
            for (int j = 0; j < 2; j++) {
                uint32_t ro = (uint32_t)(wn + j * 16 + b_row) * 128u + kb + b_kof;
                ldsm4(&bb[2 * j][0], vh + swz(ro));
            }
            #pragma unroll
            for (int mf = 0; mf < 2; mf++)
                #pragma unroll
                for (int nf = 0; nf < 4; nf++) {
                    mma_bf16(acc[mf][nf], ah[mf], bb[nf]);
                    mma_bf16(acc[mf][nf], al[mf], bb[nf]);
                }
            #pragma unroll
            for (int j = 0; j < 2; j++) {
                uint32_t ro = (uint32_t)(wn + j * 16 + b_row) * 128u + kb + b_kof;
                ldsm4(&bb[2 * j][0], vl + swz(ro));
            }
            #pragma unroll
            for (int mf = 0; mf < 2; mf++)
                #pragma unroll
                for (int nf = 0; nf < 4; nf++)
                    mma_bf16(acc[mf][nf], ah[mf], bb[nf]);
        }
    }

    // epilogue: scale by row inverse sums, write context partial
    const int er = lane >> 2;
    const int ec = (lane & 3) * 2;
    #pragma unroll
    for (int mf = 0; mf < 2; mf++) {
        float i0 = inv_s[wm + mf * 16 + er];
        float i1 = inv_s[wm + mf * 16 + er + 8];
        #pragma unroll
        for (int nf = 0; nf < 4; nf++) {
            int r = m0 + wm + mf * 16 + er;
            int cc = wn + nf * 8 + ec;
            *(float2*)(Cp + (size_t)r * DIM + cc) =
                make_float2(acc[mf][nf][0] * i0, acc[mf][nf][1] * i0);
            *(float2*)(Cp + (size_t)(r + 8) * DIM + cc) =
                make_float2(acc[mf][nf][2] * i1, acc[mf][nf][3] * i1);
        }
    }
}

// ---------------------------------------------------------------------------
// Reduce: C = Cp[0] + Cp[1]
// ---------------------------------------------------------------------------
__global__ __launch_bounds__(256) void creduce_kernel(float* __restrict__ C)
{
    const size_t N = (size_t)BATCH * LQ * DIM;          // floats
    const size_t t = (size_t)blockIdx.x * 256 + threadIdx.x;   // float4 idx
    float4 a = ((const float4*)g_Cp)[t];
    float4 b = ((const float4*)g_Cp)[t + N / 4];
    ((float4*)C)[t] = make_float4(a.x + b.x, a.y + b.y, a.z + b.z, a.w + b.w);
}

// ---------------------------------------------------------------------------
extern "C" void kernel_launch(void* const* d_in, const int* in_sizes, int n_in,
                              void* d_out, int out_size)
{
    const float* Q = (const float*)d_in[0];
    const float* K = (const float*)d_in[1];
    const float* V = (const float*)d_in[2];

    float* Wout = (float*)d_out;                            // (B,LQ,LKV)
    float* Cout = Wout + (size_t)BATCH * LQ * LKV;          // (B,LQ,DV)

    static bool attr_done = false;
    if (!attr_done) {
        cudaFuncSetAttribute(gemm1_mma_kernel,
            cudaFuncAttributeMaxDynamicSharedMemorySize, G1_SMEM);
        cudaFuncSetAttribute(gemm2_mma_kernel,
            cudaFuncAttributeMaxDynamicSharedMemorySize, G2_SMEM);
        attr_done = true;
    }

    dim3 gq((unsigned)((size_t)BATCH * LQ * DIM / 4 / 256), 2);
    qk_split_kernel<<<gq, 256>>>(Q, K);

    dim3 gt(DIM / 32, LKV / 32, BATCH);
    vt_split_kernel<<<gt, 256>>>(V);

    dim3 g1(LKV / 128, LQ / 128, BATCH);    // 16 x 16 x 8 = 2048 CTAs
    gemm1_mma_kernel<<<g1, 256, G1_SMEM>>>();

    dim3 g2(LQ / 64, BATCH, 2);             // 32 x 8 x 2 = 512 CTAs
    gemm2_mma_kernel<<<g2, 256, G2_SMEM>>>(Wout);

    creduce_kernel<<<(unsigned)((size_t)BATCH * LQ * DIM / 4 / 256), 256>>>(Cout);
}

// round 10
// speedup vs baseline: 1.0633x; 1.0633x over previous
#include <cuda_runtime.h>
#include <cuda_bf16.h>
#include <cstdint>

static constexpr int BATCH = 8;
static constexpr int LQ    = 2048;
static constexpr int LKV   = 2048;
static constexpr int DIM   = 128;   // D == DV == 128
static constexpr float SM_SCALE = 0.08838834764831845f; // 1/sqrt(128)

// Scratch: V^T pre-truncated to tf32 bit patterns, [B][DV][LKV] fp32
__device__ __align__(128) float g_Vt[(size_t)BATCH * DIM * LKV];
// per-row partial exp-sums: [B*LQ][32]  (16 n-tiles x 2 n-warps), deterministic
__device__ __align__(128) float g_partial[(size_t)BATCH * LQ * 32];

// ---------------------------------------------------------------------------
// Helpers
// ---------------------------------------------------------------------------
__device__ __forceinline__ uint32_t smem_u32(const void* p) {
    uint32_t a;
    asm("{ .reg .u64 t; cvta.to.shared.u64 t, %1; cvt.u32.u64 %0, t; }"
        : "=r"(a) : "l"(p));
    return a;
}
__device__ __forceinline__ float lds_f32(uint32_t a) {
    float v;
    asm volatile("ld.shared.f32 %0, [%1];" : "=f"(v) : "r"(a));
    return v;
}
__device__ __forceinline__ float4 lds_f32x4(uint32_t a) {
    float4 v;
    asm volatile("ld.shared.v4.f32 {%0,%1,%2,%3}, [%4];"
                 : "=f"(v.x), "=f"(v.y), "=f"(v.z), "=f"(v.w) : "r"(a));
    return v;
}
__device__ __forceinline__ uint32_t f2tf(float f) {
    uint32_t r;
    asm("cvt.rna.tf32.f32 %0, %1;" : "=r"(r) : "f"(f));
    return r;
}
__device__ __forceinline__ uint32_t ldstf(uint32_t a) {   // LDS + cvt to tf32
    return f2tf(lds_f32(a));
}
__device__ __forceinline__ uint32_t lds_u32(uint32_t a) { // raw bits (pre-truncated)
    uint32_t v;
    asm volatile("ld.shared.b32 %0, [%1];" : "=r"(v) : "r"(a));
    return v;
}
__device__ __forceinline__ void mma_tf32(float* d, const uint32_t* a, const uint32_t* b) {
    asm volatile("mma.sync.aligned.m16n8k8.row.col.f32.tf32.tf32.f32 "
                 "{%0,%1,%2,%3}, {%4,%5,%6,%7}, {%8,%9}, {%0,%1,%2,%3};"
                 : "+f"(d[0]), "+f"(d[1]), "+f"(d[2]), "+f"(d[3])
                 : "r"(a[0]), "r"(a[1]), "r"(a[2]), "r"(a[3]), "r"(b[0]), "r"(b[1]));
}
#define CP_ASYNC16(dst, src) \
    asm volatile("cp.async.cg.shared.global [%0], [%1], 16;" :: "r"(dst), "l"(src) : "memory")
#define CP_COMMIT()  asm volatile("cp.async.commit_group;" ::: "memory")
#define CP_WAIT(n)   asm volatile("cp.async.wait_group %0;" :: "n"(n) : "memory")

// ---------------------------------------------------------------------------
// Prep: transpose V and pre-truncate to tf32:  V[b][k][n] -> g_Vt[b][n][k]
// ---------------------------------------------------------------------------
__global__ __launch_bounds__(256) void vt_tf32_kernel(const float* __restrict__ V)
{
    __shared__ float t[32][33];
    const int b  = blockIdx.z;
    const int k0 = blockIdx.y * 32;
    const int n0 = blockIdx.x * 32;
    const int tx = threadIdx.x & 31;
    const int ty = threadIdx.x >> 5;   // 0..7

    #pragma unroll
    for (int i = 0; i < 4; i++) {
        int k = ty + i * 8;
        t[k][tx] = V[((size_t)b * LKV + k0 + k) * DIM + n0 + tx];
    }
    __syncthreads();
    #pragma unroll
    for (int i = 0; i < 4; i++) {
        int n = ty + i * 8;
        uint32_t bits = f2tf(t[tx][n]);
        *(uint32_t*)&g_Vt[((size_t)b * DIM + n0 + n) * LKV + k0 + tx] = bits;
    }
}

// ---------------------------------------------------------------------------
// GEMM1: E = exp(scale * Q K^T) via single-pass tf32 mma.  CTA tile 128x128,
// 8 warps (warp tile 32x64).  K=128 in 4 chunks of 32, 2-stage cp.async
// pipeline, padded-linear smem (row = 32 floats + 4 pad = 144B).
// Writes E fp32 directly into the weights region + per-row partial sums.
// ---------------------------------------------------------------------------
static constexpr int G1_ROWB = 144;              // bytes per smem row
static constexpr int G1_TILE = 128 * G1_ROWB;    // 18432 per operand
static constexpr int G1_STAGE = 2 * G1_TILE;     // Q + K
static constexpr int G1_SMEM = 1024 + 2 * G1_STAGE;

__global__ __launch_bounds__(256, 2) void gemm1_mma_kernel(
    const float* __restrict__ Q, const float* __restrict__ K,
    float* __restrict__ S)
{
    extern __shared__ char smem[];
    const uint32_t sb = (smem_u32(smem) + 1023u) & ~1023u;

    const int tid  = threadIdx.x;
    const int lane = tid & 31;
    const int w    = tid >> 5;
    const int wm   = (w >> 1) * 32;   // 4 warps in M
    const int wn   = (w & 1) * 64;    // 2 warps in N

    const int b  = blockIdx.z;
    const int m0 = blockIdx.y * 128;
    const int n0 = blockIdx.x * 128;

    const float* Qb = Q + ((size_t)b * LQ  + m0) * DIM;
    const float* Kb = K + ((size_t)b * LKV + n0) * DIM;
    float*       Sb = S + (size_t)b * LQ * LKV;

    // stage: Q at +0, K at +G1_TILE; 128 rows x 8 16B-units each
    auto load_chunk = [&](int c, int stage) {
        const int k0 = c * 32;
        const uint32_t base = sb + (uint32_t)stage * G1_STAGE;
        #pragma unroll
        for (int i = 0; i < 4; i++) {
            int u = i * 256 + tid;          // 0..1023
            int row = u >> 3, un = (u & 7) * 16;
            uint32_t off = (uint32_t)row * G1_ROWB + un;
            CP_ASYNC16(base + off,           Qb + (size_t)row * DIM + k0 + (un >> 2));
            CP_ASYNC16(base + G1_TILE + off, Kb + (size_t)row * DIM + k0 + (un >> 2));
        }
    };

    float acc[2][8][4] = {};

    const uint32_t g = lane >> 2;     // 0..7
    const uint32_t cc4 = (lane & 3);  // 0..3

    load_chunk(0, 0);
    CP_COMMIT();

    for (int c = 0; c < 4; c++) {
        CP_WAIT(0);
        __syncthreads();   // chunk c resident; all warps past chunk c-1

        if (c < 3) { load_chunk(c + 1, (c + 1) & 1); CP_COMMIT(); }

        const uint32_t base = sb + (uint32_t)(c & 1) * G1_STAGE;
        const uint32_t QS = base, KS = base + G1_TILE;

        #pragma unroll
        for (int ks = 0; ks < 4; ks++) {
            const uint32_t kb = ks * 8;   // k offset in floats
            uint32_t A[2][4], B[8][2];

            #pragma unroll
            for (int mf = 0; mf < 2; mf++) {
                uint32_t a0 = QS + (uint32_t)(wm + mf * 16 + g) * G1_ROWB + (kb + cc4) * 4;
                A[mf][0] = ldstf(a0);
                A[mf][1] = ldstf(a0 + 8 * G1_ROWB);
                A[mf][2] = ldstf(a0 + 16);
                A[mf][3] = ldstf(a0 + 8 * G1_ROWB + 16);
            }
            #pragma unroll
            for (int nf = 0; nf < 8; nf++) {
                uint32_t b0 = KS + (uint32_t)(wn + nf * 8 + g) * G1_ROWB + (kb + cc4) * 4;
                B[nf][0] = ldstf(b0);
                B[nf][1] = ldstf(b0 + 16);
            }
            #pragma unroll
            for (int mf = 0; mf < 2; mf++)
                #pragma unroll
                for (int nf = 0; nf < 8; nf++)
                    mma_tf32(acc[mf][nf], A[mf], B[nf]);
        }
    }

    // epilogue: scale, exp, store E fp32; per-row partial sums (deterministic)
    const int er = lane >> 2;
    const int ec = (lane & 3) * 2;
    float rsum[2][2] = {{0.f, 0.f}, {0.f, 0.f}};
    #pragma unroll
    for (int mf = 0; mf < 2; mf++)
        #pragma unroll
        for (int nf = 0; nf < 8; nf++) {
            float e0 = __expf(fminf(acc[mf][nf][0] * SM_SCALE, 80.f));
            float e1 = __expf(fminf(acc[mf][nf][1] * SM_SCALE, 80.f));
            float e2 = __expf(fminf(acc[mf][nf][2] * SM_SCALE, 80.f));
            float e3 = __expf(fminf(acc[mf][nf][3] * SM_SCALE, 80.f));
            int r = m0 + wm + mf * 16 + er;
            int nn = n0 + wn + nf * 8 + ec;
            *(float2*)(Sb + (size_t)r * LKV + nn)       = make_float2(e0, e1);
            *(float2*)(Sb + (size_t)(r + 8) * LKV + nn) = make_float2(e2, e3);
            rsum[mf][0] += e0 + e1;
            rsum[mf][1] += e2 + e3;
        }
    #pragma unroll
    for (int mf = 0; mf < 2; mf++)
        #pragma unroll
        for (int h = 0; h < 2; h++) {
            float v = rsum[mf][h];
            v += __shfl_xor_sync(0xffffffffu, v, 1);
            v += __shfl_xor_sync(0xffffffffu, v, 2);
            if ((lane & 3) == 0) {
                int row = m0 + wm + mf * 16 + h * 8 + er;
                g_partial[((size_t)b * LQ + row) * 32 + blockIdx.x * 2 + (w & 1)] = v;
            }
        }
}

// ---------------------------------------------------------------------------
// GEMM2: C = diag(inv) * (E V); W = E*inv written in place over E (final
// fp32 weights).  CTA tile 64(M) x 128(N=DV), K=2048 in 32 chunks of 64.
// tf32 single-pass; E fp32 read from W region; V^T scratch pre-truncated.
// 2-stage cp.async pipeline, one barrier per chunk, prefetch-after-sync
// (prefetch of chunk c+1 reads E cols disjoint from chunk c's W writes).
// ---------------------------------------------------------------------------
static constexpr int G2_ROWB = 272;               // 64 floats + 4 pad
static constexpr int G2_ETILE = 64 * G2_ROWB;     // 17408
static constexpr int G2_VTILE = 128 * G2_ROWB;    // 34816
static constexpr int G2_STAGE = G2_ETILE + G2_VTILE;   // 52224
static constexpr int G2_SMEM = 1024 + 2 * G2_STAGE + 256;

__global__ __launch_bounds__(256, 2) void gemm2_mma_kernel(
    float* __restrict__ W, float* __restrict__ C)
{
    extern __shared__ char smem[];
    const uint32_t sb = (smem_u32(smem) + 1023u) & ~1023u;
    float* inv_s = (float*)(smem + (sb - smem_u32(smem)) + 2 * G2_STAGE);

    const int tid  = threadIdx.x;
    const int lane = tid & 31;
    const int w    = tid >> 5;
    const int wm   = (w >> 2) * 32;   // 2 warps in M
    const int wn   = (w & 3) * 32;    // 4 warps in N

    const int m0 = blockIdx.x * 64;
    const int b  = blockIdx.y;

    float* Wb = W + ((size_t)b * LQ + m0) * LKV;          // E in, W out
    const float* Vt = g_Vt + (size_t)b * DIM * LKV;
    float* Cb = C + (size_t)b * LQ * DIM;

    // row inverse sums (deterministic reduction of 32 partials)
    if (tid < 64) {
        const float* p = g_partial + ((size_t)b * LQ + m0 + tid) * 32;
        float s = 0.f;
        #pragma unroll
        for (int j = 0; j < 32; j++) s += p[j];
        inv_s[tid] = 1.0f / s;
    }

    // stage: E at +0 (64 rows x 16 units), V at +G2_ETILE (128 rows x 16 units)
    auto load_chunk = [&](int c, int stage) {
        const int k0 = c * 64;
        const uint32_t base = sb + (uint32_t)stage * G2_STAGE;
        #pragma unroll
        for (int i = 0; i < 4; i++) {
            int u = i * 256 + tid;          // 0..1023
            int row = u >> 4, un = (u & 15) * 16;
            uint32_t off = (uint32_t)row * G2_ROWB + un;
            CP_ASYNC16(base + off, Wb + (size_t)row * LKV + k0 + (un >> 2));
        }
        #pragma unroll
        for (int i = 0; i < 8; i++) {
            int u = i * 256 + tid;          // 0..2047
            int row = u >> 4, un = (u & 15) * 16;
            uint32_t off = (uint32_t)row * G2_ROWB + un;
            CP_ASYNC16(base + G2_ETILE + off, Vt + (size_t)row * LKV + k0 + (un >> 2));
        }
    };

    float acc[2][4][4] = {};

    const uint32_t g = lane >> 2;
    const uint32_t cc4 = (lane & 3);

    load_chunk(0, 0);
    CP_COMMIT();

    for (int c = 0; c < 32; c++) {
        CP_WAIT(0);
        __syncthreads();   // chunk c resident; all warps past chunk c-1

        if (c < 31) { load_chunk(c + 1, (c + 1) & 1); CP_COMMIT(); }

        const int k0 = c * 64;
        const uint32_t base = sb + (uint32_t)(c & 1) * G2_STAGE;
        const uint32_t ES = base, VS = base + G2_ETILE;

        // W = E * inv  -> final fp32 weights (overlaps MMA below)
        #pragma unroll
        for (int i = 0; i < 4; i++) {
            int u = i * 256 + tid;
            int row = u >> 4, un = (u & 15) * 16;
            float4 e = lds_f32x4(ES + (uint32_t)row * G2_ROWB + un);
            float inv = inv_s[row];
            *(float4*)(Wb + (size_t)row * LKV + k0 + (un >> 2)) =
                make_float4(e.x * inv, e.y * inv, e.z * inv, e.w * inv);
        }

        #pragma unroll
        for (int ks = 0; ks < 8; ks++) {
            const uint32_t kb = ks * 8;
            uint32_t A[2][4], B[4][2];

            #pragma unroll
            for (int mf = 0; mf < 2; mf++) {
                uint32_t a0 = ES + (uint32_t)(wm + mf * 16 + g) * G2_ROWB + (kb + cc4) * 4;
                A[mf][0] = ldstf(a0);
                A[mf][1] = ldstf(a0 + 8 * G2_ROWB);
                A[mf][2] = ldstf(a0 + 16);
                A[mf][3] = ldstf(a0 + 8 * G2_ROWB + 16);
            }
            #pragma unroll
            for (int nf = 0; nf < 4; nf++) {
                uint32_t b0 = VS + (uint32_t)(wn + nf * 8 + g) * G2_ROWB + (kb + cc4) * 4;
                B[nf][0] = lds_u32(b0);        // pre-truncated tf32 bits
                B[nf][1] = lds_u32(b0 + 16);
            }
            #pragma unroll
            for (int mf = 0; mf < 2; mf++)
                #pragma unroll
                for (int nf = 0; nf < 4; nf++)
                    mma_tf32(acc[mf][nf], A[mf], B[nf]);
        }
    }

    // epilogue: scale by row inverse sums, write context
    const int er = lane >> 2;
    const int ec = (lane & 3) * 2;
    #pragma unroll
    for (int mf = 0; mf < 2; mf++) {
        float i0 = inv_s[wm + mf * 16 + er];
        float i1 = inv_s[wm + mf * 16 + er + 8];
        #pragma unroll
        for (int nf = 0; nf < 4; nf++) {
            int r = m0 + wm + mf * 16 + er;
            int nn = wn + nf * 8 + ec;
            *(float2*)(Cb + (size_t)r * DIM + nn) =
                make_float2(acc[mf][nf][0] * i0, acc[mf][nf][1] * i0);
            *(float2*)(Cb + (size_t)(r + 8) * DIM + nn) =
                make_float2(acc[mf][nf][2] * i1, acc[mf][nf][3] * i1);
        }
    }
}

// ---------------------------------------------------------------------------
extern "C" void kernel_launch(void* const* d_in, const int* in_sizes, int n_in,
                              void* d_out, int out_size)
{
    const float* Q = (const float*)d_in[0];
    const float* K = (const float*)d_in[1];
    const float* V = (const float*)d_in[2];

    float* Wout = (float*)d_out;                            // (B,LQ,LKV)
    float* Cout = Wout + (size_t)BATCH * LQ * LKV;          // (B,LQ,DV)

    static bool attr_done = false;
    if (!attr_done) {
        cudaFuncSetAttribute(gemm1_mma_kernel,
            cudaFuncAttributeMaxDynamicSharedMemorySize, G1_SMEM);
        cudaFuncSetAttribute(gemm2_mma_kernel,
            cudaFuncAttributeMaxDynamicSharedMemorySize, G2_SMEM);
        attr_done = true;
    }

    dim3 gt(DIM / 32, LKV / 32, BATCH);
    vt_tf32_kernel<<<gt, 256>>>(V);

    dim3 g1(LKV / 128, LQ / 128, BATCH);    // 16 x 16 x 8 = 2048 CTAs
    gemm1_mma_kernel<<<g1, 256, G1_SMEM>>>(Q, K, Wout);

    dim3 g2(LQ / 64, BATCH);                // 32 x 8 = 256 CTAs
    gemm2_mma_kernel<<<g2, 256, G2_SMEM>>>(Wout, Cout);
}

// round 11
// speedup vs baseline: 1.1018x; 1.0362x over previous
#include <cuda_runtime.h>
#include <cuda_bf16.h>
#include <cstdint>

static constexpr int BATCH = 8;
static constexpr int LQ    = 2048;
static constexpr int LKV   = 2048;
static constexpr int DIM   = 128;   // D == DV == 128
static constexpr float SM_SCALE = 0.08838834764831845f; // 1/sqrt(128)

// Scratch (device globals; no runtime allocation allowed)
__device__ __align__(128) float g_Qt[(size_t)BATCH * LQ  * DIM];   // tf32 bits
__device__ __align__(128) float g_Kt[(size_t)BATCH * LKV * DIM];   // tf32 bits
__device__ __align__(128) float g_Vt[(size_t)BATCH * DIM * LKV];   // V^T, tf32 bits
// per-row partial exp-sums: [B*LQ][32]  (16 n-tiles x 2 n-warps), deterministic
__device__ __align__(128) float g_partial[(size_t)BATCH * LQ * 32];

// ---------------------------------------------------------------------------
// Helpers
// ---------------------------------------------------------------------------
__device__ __forceinline__ uint32_t smem_u32(const void* p) {
    uint32_t a;
    asm("{ .reg .u64 t; cvta.to.shared.u64 t, %1; cvt.u32.u64 %0, t; }"
        : "=r"(a) : "l"(p));
    return a;
}
__device__ __forceinline__ float4 lds_f32x4(uint32_t a) {
    float4 v;
    asm volatile("ld.shared.v4.f32 {%0,%1,%2,%3}, [%4];"
                 : "=f"(v.x), "=f"(v.y), "=f"(v.z), "=f"(v.w) : "r"(a));
    return v;
}
__device__ __forceinline__ uint32_t f2tf(float f) {
    uint32_t r;
    asm("cvt.rna.tf32.f32 %0, %1;" : "=r"(r) : "f"(f));
    return r;
}
__device__ __forceinline__ uint32_t lds_u32(uint32_t a) { // raw tf32 bits
    uint32_t v;
    asm volatile("ld.shared.b32 %0, [%1];" : "=r"(v) : "r"(a));
    return v;
}
__device__ __forceinline__ void mma_tf32(float* d, const uint32_t* a, const uint32_t* b) {
    asm volatile("mma.sync.aligned.m16n8k8.row.col.f32.tf32.tf32.f32 "
                 "{%0,%1,%2,%3}, {%4,%5,%6,%7}, {%8,%9}, {%0,%1,%2,%3};"
                 : "+f"(d[0]), "+f"(d[1]), "+f"(d[2]), "+f"(d[3])
                 : "r"(a[0]), "r"(a[1]), "r"(a[2]), "r"(a[3]), "r"(b[0]), "r"(b[1]));
}
#define CP_ASYNC16(dst, src) \
    asm volatile("cp.async.cg.shared.global [%0], [%1], 16;" :: "r"(dst), "l"(src) : "memory")
#define CP_COMMIT()  asm volatile("cp.async.commit_group;" ::: "memory")
#define CP_WAIT(n)   asm volatile("cp.async.wait_group %0;" :: "n"(n) : "memory")

// ---------------------------------------------------------------------------
// Prep A: elementwise tf32 truncation of Q and K into scratch
// ---------------------------------------------------------------------------
__global__ __launch_bounds__(256) void qk_tf32_kernel(
    const float* __restrict__ Q, const float* __restrict__ K)
{
    const size_t t = (size_t)blockIdx.x * 256 + threadIdx.x;   // float4 index
    const bool isK = blockIdx.y != 0;
    const float4 v = ((const float4*)(isK ? K : Q))[t];
    uint4 o = make_uint4(f2tf(v.x), f2tf(v.y), f2tf(v.z), f2tf(v.w));
    ((uint4*)(isK ? g_Kt : g_Qt))[t] = o;
}

// ---------------------------------------------------------------------------
// Prep B: transpose V and pre-truncate to tf32:  V[b][k][n] -> g_Vt[b][n][k]
// ---------------------------------------------------------------------------
__global__ __launch_bounds__(256) void vt_tf32_kernel(const float* __restrict__ V)
{
    __shared__ float t[32][33];
    const int b  = blockIdx.z;
    const int k0 = blockIdx.y * 32;
    const int n0 = blockIdx.x * 32;
    const int tx = threadIdx.x & 31;
    const int ty = threadIdx.x >> 5;   // 0..7

    #pragma unroll
    for (int i = 0; i < 4; i++) {
        int k = ty + i * 8;
        t[k][tx] = V[((size_t)b * LKV + k0 + k) * DIM + n0 + tx];
    }
    __syncthreads();
    #pragma unroll
    for (int i = 0; i < 4; i++) {
        int n = ty + i * 8;
        uint32_t bits = f2tf(t[tx][n]);
        *(uint32_t*)&g_Vt[((size_t)b * DIM + n0 + n) * LKV + k0 + tx] = bits;
    }
}

// ---------------------------------------------------------------------------
// GEMM1: E = exp(scale * Q K^T), tf32 single-pass, operands pre-truncated.
// CTA tile 128x128, 8 warps (warp tile 32x64).  K=128 in 4 chunks of 32,
// 3-stage cp.async pipeline, padded-linear smem (row = 32 floats + 4 pad).
// Writes E (tf32-rounded fp32) into the weights region + per-row partials.
// ---------------------------------------------------------------------------
static constexpr int G1_ROWB  = 144;              // bytes per smem row
static constexpr int G1_TILE  = 128 * G1_ROWB;    // 18432 per operand
static constexpr int G1_STAGE = 2 * G1_TILE;      // Q + K = 36864
static constexpr int G1_SMEM  = 1024 + 3 * G1_STAGE;   // 111616

__global__ __launch_bounds__(256, 2) void gemm1_mma_kernel(float* __restrict__ S)
{
    extern __shared__ char smem[];
    const uint32_t sb = (smem_u32(smem) + 1023u) & ~1023u;

    const int tid  = threadIdx.x;
    const int lane = tid & 31;
    const int w    = tid >> 5;
    const int wm   = (w >> 1) * 32;   // 4 warps in M
    const int wn   = (w & 1) * 64;    // 2 warps in N

    const int b  = blockIdx.z;
    const int m0 = blockIdx.y * 128;
    const int n0 = blockIdx.x * 128;

    const float* Qb = g_Qt + ((size_t)b * LQ  + m0) * DIM;
    const float* Kb = g_Kt + ((size_t)b * LKV + n0) * DIM;
    float*       Sb = S + (size_t)b * LQ * LKV;

    auto load_chunk = [&](int c, int stage) {
        const int k0 = c * 32;
        const uint32_t base = sb + (uint32_t)stage * G1_STAGE;
        #pragma unroll
        for (int i = 0; i < 4; i++) {
            int u = i * 256 + tid;          // 0..1023
            int row = u >> 3, un = (u & 7) * 16;
            uint32_t off = (uint32_t)row * G1_ROWB + un;
            CP_ASYNC16(base + off,           Qb + (size_t)row * DIM + k0 + (un >> 2));
            CP_ASYNC16(base + G1_TILE + off, Kb + (size_t)row * DIM + k0 + (un >> 2));
        }
    };

    float acc[2][8][4] = {};

    const uint32_t g = lane >> 2;     // 0..7
    const uint32_t cc4 = (lane & 3);  // 0..3

    load_chunk(0, 0); CP_COMMIT();
    load_chunk(1, 1); CP_COMMIT();

    for (int c = 0; c < 4; c++) {
        if (c < 3) { CP_WAIT(1); } else { CP_WAIT(0); }
        __syncthreads();   // chunk c resident; all warps past chunk c-1

        if (c < 2) { load_chunk(c + 2, (c + 2) % 3); CP_COMMIT(); }

        const uint32_t base = sb + (uint32_t)(c % 3) * G1_STAGE;
        const uint32_t QS = base, KS = base + G1_TILE;

        #pragma unroll
        for (int ks = 0; ks < 4; ks++) {
            const uint32_t kb = ks * 8;   // k offset in floats
            uint32_t A[2][4], B[8][2];

            #pragma unroll
            for (int mf = 0; mf < 2; mf++) {
                uint32_t a0 = QS + (uint32_t)(wm + mf * 16 + g) * G1_ROWB + (kb + cc4) * 4;
                A[mf][0] = lds_u32(a0);
                A[mf][1] = lds_u32(a0 + 8 * G1_ROWB);
                A[mf][2] = lds_u32(a0 + 16);
                A[mf][3] = lds_u32(a0 + 8 * G1_ROWB + 16);
            }
            #pragma unroll
            for (int nf = 0; nf < 8; nf++) {
                uint32_t b0 = KS + (uint32_t)(wn + nf * 8 + g) * G1_ROWB + (kb + cc4) * 4;
                B[nf][0] = lds_u32(b0);
                B[nf][1] = lds_u32(b0 + 16);
            }
            #pragma unroll
            for (int mf = 0; mf < 2; mf++)
                #pragma unroll
                for (int nf = 0; nf < 8; nf++)
                    mma_tf32(acc[mf][nf], A[mf], B[nf]);
        }
    }

    // epilogue: scale, exp, round to tf32 (so gemm2 needs no cvt), store;
    // per-row partial sums over the ROUNDED values (consistent normalization)
    const int er = lane >> 2;
    const int ec = (lane & 3) * 2;
    float rsum[2][2] = {{0.f, 0.f}, {0.f, 0.f}};
    #pragma unroll
    for (int mf = 0; mf < 2; mf++)
        #pragma unroll
        for (int nf = 0; nf < 8; nf++) {
            float e0 = __uint_as_float(f2tf(__expf(fminf(acc[mf][nf][0] * SM_SCALE, 80.f))));
            float e1 = __uint_as_float(f2tf(__expf(fminf(acc[mf][nf][1] * SM_SCALE, 80.f))));
            float e2 = __uint_as_float(f2tf(__expf(fminf(acc[mf][nf][2] * SM_SCALE, 80.f))));
            float e3 = __uint_as_float(f2tf(__expf(fminf(acc[mf][nf][3] * SM_SCALE, 80.f))));
            int r = m0 + wm + mf * 16 + er;
            int nn = n0 + wn + nf * 8 + ec;
            *(float2*)(Sb + (size_t)r * LKV + nn)       = make_float2(e0, e1);
            *(float2*)(Sb + (size_t)(r + 8) * LKV + nn) = make_float2(e2, e3);
            rsum[mf][0] += e0 + e1;
            rsum[mf][1] += e2 + e3;
        }
    #pragma unroll
    for (int mf = 0; mf < 2; mf++)
        #pragma unroll
        for (int h = 0; h < 2; h++) {
            float v = rsum[mf][h];
            v += __shfl_xor_sync(0xffffffffu, v, 1);
            v += __shfl_xor_sync(0xffffffffu, v, 2);
            if ((lane & 3) == 0) {
                int row = m0 + wm + mf * 16 + h * 8 + er;
                g_partial[((size_t)b * LQ + row) * 32 + blockIdx.x * 2 + (w & 1)] = v;
            }
        }
}

// ---------------------------------------------------------------------------
// GEMM2: C = diag(inv) * (E V); W = E*inv written in place over E (final
// fp32 weights).  CTA tile 64(M) x 128(N=DV), K=2048 in 64 chunks of 32,
// 4-stage cp.async pipeline.  E is tf32-rounded at source -> raw-bits LDS,
// zero conversions in the hot loop.  One barrier per chunk; prefetch of
// chunk c+3 issued after the barrier proving all warps left chunk c-1
// (whose stage it reuses).
// ---------------------------------------------------------------------------
static constexpr int G2_ROWB  = 144;               // 32 floats + 4 pad
static constexpr int G2_ETILE = 64 * G2_ROWB;      // 9216
static constexpr int G2_VTILE = 128 * G2_ROWB;     // 18432
static constexpr int G2_STAGE = G2_ETILE + G2_VTILE;    // 27648
static constexpr int G2_SMEM  = 1024 + 4 * G2_STAGE + 256;  // 112128

__global__ __launch_bounds__(256, 2) void gemm2_mma_kernel(
    float* __restrict__ W, float* __restrict__ C)
{
    extern __shared__ char smem[];
    const uint32_t sb = (smem_u32(smem) + 1023u) & ~1023u;
    float* inv_s = (float*)(smem + (sb - smem_u32(smem)) + 4 * G2_STAGE);

    const int tid  = threadIdx.x;
    const int lane = tid & 31;
    const int w    = tid >> 5;
    const int wm   = (w >> 2) * 32;   // 2 warps in M
    const int wn   = (w & 3) * 32;    // 4 warps in N

    const int m0 = blockIdx.x * 64;
    const int b  = blockIdx.y;

    float* Wb = W + ((size_t)b * LQ + m0) * LKV;          // E in, W out
    const float* Vt = g_Vt + (size_t)b * DIM * LKV;
    float* Cb = C + (size_t)b * LQ * DIM;

    // row inverse sums (deterministic reduction of 32 partials)
    if (tid < 64) {
        const float* p = g_partial + ((size_t)b * LQ + m0 + tid) * 32;
        float s = 0.f;
        #pragma unroll
        for (int j = 0; j < 32; j++) s += p[j];
        inv_s[tid] = 1.0f / s;
    }

    auto load_chunk = [&](int c, int stage) {
        const int k0 = c * 32;
        const uint32_t base = sb + (uint32_t)stage * G2_STAGE;
        #pragma unroll
        for (int i = 0; i < 2; i++) {       // E: 64 rows x 8 16B-units
            int u = i * 256 + tid;
            int row = u >> 3, un = (u & 7) * 16;
            uint32_t off = (uint32_t)row * G2_ROWB + un;
            CP_ASYNC16(base + off, Wb + (size_t)row * LKV + k0 + (un >> 2));
        }
        #pragma unroll
        for (int i = 0; i < 4; i++) {       // V: 128 rows x 8 16B-units
            int u = i * 256 + tid;
            int row = u >> 3, un = (u & 7) * 16;
            uint32_t off = (uint32_t)row * G2_ROWB + un;
            CP_ASYNC16(base + G2_ETILE + off, Vt + (size_t)row * LKV + k0 + (un >> 2));
        }
    };

    float acc[2][4][4] = {};

    const uint32_t g = lane >> 2;
    const uint32_t cc4 = (lane & 3);

    load_chunk(0, 0); CP_COMMIT();
    load_chunk(1, 1); CP_COMMIT();
    load_chunk(2, 2); CP_COMMIT();

    for (int c = 0; c < 64; c++) {
        if (c <= 61)      { CP_WAIT(2); }
        else if (c == 62) { CP_WAIT(1); }
        else              { CP_WAIT(0); }
        __syncthreads();   // chunk c resident; all warps past chunk c-1

        if (c < 61) { load_chunk(c + 3, (c + 3) & 3); CP_COMMIT(); }

        const int k0 = c * 32;
        const uint32_t base = sb + (uint32_t)(c & 3) * G2_STAGE;
        const uint32_t ES = base, VS = base + G2_ETILE;

        // W = E * inv  -> final fp32 weights (overlaps MMA below)
        #pragma unroll
        for (int i = 0; i < 2; i++) {
            int u = i * 256 + tid;
            int row = u >> 3, un = (u & 7) * 16;
            float4 e = lds_f32x4(ES + (uint32_t)row * G2_ROWB + un);
            float inv = inv_s[row];
            *(float4*)(Wb + (size_t)row * LKV + k0 + (un >> 2)) =
                make_float4(e.x * inv, e.y * inv, e.z * inv, e.w * inv);
        }

        #pragma unroll
        for (int ks = 0; ks < 4; ks++) {
            const uint32_t kb = ks * 8;
            uint32_t A[2][4], B[4][2];

            #pragma unroll
            for (int mf = 0; mf < 2; mf++) {
                uint32_t a0 = ES + (uint32_t)(wm + mf * 16 + g) * G2_ROWB + (kb + cc4) * 4;
                A[mf][0] = lds_u32(a0);
                A[mf][1] = lds_u32(a0 + 8 * G2_ROWB);
                A[mf][2] = lds_u32(a0 + 16);
                A[mf][3] = lds_u32(a0 + 8 * G2_ROWB + 16);
            }
            #pragma unroll
            for (int nf = 0; nf < 4; nf++) {
                uint32_t b0 = VS + (uint32_t)(wn + nf * 8 + g) * G2_ROWB + (kb + cc4) * 4;
                B[nf][0] = lds_u32(b0);
                B[nf][1] = lds_u32(b0 + 16);
            }
            #pragma unroll
            for (int mf = 0; mf < 2; mf++)
                #pragma unroll
                for (int nf = 0; nf < 4; nf++)
                    mma_tf32(acc[mf][nf], A[mf], B[nf]);
        }
    }

    // epilogue: scale by row inverse sums, write context
    const int er = lane >> 2;
    const int ec = (lane & 3) * 2;
    #pragma unroll
    for (int mf = 0; mf < 2; mf++) {
        float i0 = inv_s[wm + mf * 16 + er];
        float i1 = inv_s[wm + mf * 16 + er + 8];
        #pragma unroll
        for (int nf = 0; nf < 4; nf++) {
            int r = m0 + wm + mf * 16 + er;
            int nn = wn + nf * 8 + ec;
            *(float2*)(Cb + (size_t)r * DIM + nn) =
                make_float2(acc[mf][nf][0] * i0, acc[mf][nf][1] * i0);
            *(float2*)(Cb + (size_t)(r + 8) * DIM + nn) =
                make_float2(acc[mf][nf][2] * i1, acc[mf][nf][3] * i1);
        }
    }
}

// ---------------------------------------------------------------------------
extern "C" void kernel_launch(void* const* d_in, const int* in_sizes, int n_in,
                              void* d_out, int out_size)
{
    const float* Q = (const float*)d_in[0];
    const float* K = (const float*)d_in[1];
    const float* V = (const float*)d_in[2];

    float* Wout = (float*)d_out;                            // (B,LQ,LKV)
    float* Cout = Wout + (size_t)BATCH * LQ * LKV;          // (B,LQ,DV)

    static bool attr_done = false;
    if (!attr_done) {
        cudaFuncSetAttribute(gemm1_mma_kernel,
            cudaFuncAttributeMaxDynamicSharedMemorySize, G1_SMEM);
        cudaFuncSetAttribute(gemm2_mma_kernel,
            cudaFuncAttributeMaxDynamicSharedMemorySize, G2_SMEM);
        attr_done = true;
    }

    dim3 gq((unsigned)((size_t)BATCH * LQ * DIM / 4 / 256), 2);
    qk_tf32_kernel<<<gq, 256>>>(Q, K);

    dim3 gt(DIM / 32, LKV / 32, BATCH);
    vt_tf32_kernel<<<gt, 256>>>(V);

    dim3 g1(LKV / 128, LQ / 128, BATCH);    // 16 x 16 x 8 = 2048 CTAs
    gemm1_mma_kernel<<<g1, 256, G1_SMEM>>>(Wout);

    dim3 g2(LQ / 64, BATCH);                // 32 x 8 = 256 CTAs
    gemm2_mma_kernel<<<g2, 256, G2_SMEM>>>(Wout, Cout);
}